// round 1
// baseline (speedup 1.0000x reference)
#include <cuda_runtime.h>
#include <cstdint>

// Problem constants
#define HH 16
#define NN 8192
#define DD 256
#define II 1024

// Tiling
#define BM 64      // rows of x per block
#define BI 128     // I-chunk
#define BKS 32     // K staging step
#define NTHREADS 256

// SMEM strides (floats), padded so stride % 32 == 8 -> conflict-free fragment gathers
#define SX_LD  264   // sx[64][264]
#define W1_LD  136   // w1s[32][136]
#define HS_LD  136   // hs[64][136]
#define W2_LD  264   // w2s[32][264]

#define SMEM_FLOATS (64*SX_LD + 32*W1_LD + 64*HS_LD + 32*W2_LD)
#define SMEM_BYTES  (SMEM_FLOATS * 4)

__device__ __forceinline__ uint32_t f32_tf32(float x) {
    uint32_t u;
    asm("cvt.rna.tf32.f32 %0, %1;" : "=r"(u) : "f"(x));
    return u;
}

__device__ __forceinline__ float4 tf32x4(float4 v) {
    float4 o;
    o.x = __uint_as_float(f32_tf32(v.x));
    o.y = __uint_as_float(f32_tf32(v.y));
    o.z = __uint_as_float(f32_tf32(v.z));
    o.w = __uint_as_float(f32_tf32(v.w));
    return o;
}

__device__ __forceinline__ void mma_tf32_16x8x8(float c[4], const uint32_t a[4], const uint32_t b[2]) {
    asm volatile(
        "mma.sync.aligned.m16n8k8.row.col.f32.tf32.tf32.f32 "
        "{%0,%1,%2,%3}, {%4,%5,%6,%7}, {%8,%9}, {%0,%1,%2,%3};\n"
        : "+f"(c[0]), "+f"(c[1]), "+f"(c[2]), "+f"(c[3])
        : "r"(a[0]), "r"(a[1]), "r"(a[2]), "r"(a[3]),
          "r"(b[0]), "r"(b[1]));
}

__device__ __forceinline__ float silu(float v) {
    return v / (1.0f + expf(-v));
}

__global__ __launch_bounds__(NTHREADS, 1)
void mlp_fused_tf32_kernel(const float* __restrict__ x,
                           const float* __restrict__ w1,
                           const float* __restrict__ w2,
                           float* __restrict__ out) {
    extern __shared__ float sm[];
    float* sx  = sm;                   // [64][SX_LD]  x tile (tf32-rounded)
    float* w1s = sx  + 64 * SX_LD;     // [32][W1_LD]  staged w1 K-slab
    float* hs  = w1s + 32 * W1_LD;     // [64][HS_LD]  silu(z) chunk (tf32-rounded)
    float* w2s = hs  + 64 * HS_LD;     // [32][W2_LD]  staged w2 K-slab

    const int tid  = threadIdx.x;
    const int head = blockIdx.y;
    const int n0   = blockIdx.x * BM;

    const int wid  = tid >> 5;
    const int lane = tid & 31;
    const int g    = lane >> 2;   // group row (0..7)
    const int tg   = lane & 3;    // thread-in-group (0..3)
    const int wm   = wid >> 2;    // warp row (0..1)
    const int wn   = wid & 3;     // warp col (0..3)

    // ---------- load x tile (once), rounding to tf32 ----------
    {
        const float* xb = x + ((size_t)head * NN + n0) * DD;
        #pragma unroll
        for (int i = tid; i < BM * DD / 4; i += NTHREADS) {
            int row = i >> 6;
            int c4  = (i & 63) << 2;
            float4 v = *(const float4*)(xb + row * DD + c4);
            *(float4*)(sx + row * SX_LD + c4) = tf32x4(v);
        }
    }
    __syncthreads();

    // persistent output accumulator: warp tile 32x64 => 2 m-tiles x 8 n-tiles
    float acc2[2][8][4];
    #pragma unroll
    for (int mt = 0; mt < 2; mt++)
        #pragma unroll
        for (int nt = 0; nt < 8; nt++)
            #pragma unroll
            for (int r = 0; r < 4; r++)
                acc2[mt][nt][r] = 0.0f;

    for (int ic = 0; ic < II; ic += BI) {
        // ================= GEMM1: z[64][128] = sx[64][256] @ w1[:,ic:ic+128] =================
        float acc1[2][4][4];
        #pragma unroll
        for (int mt = 0; mt < 2; mt++)
            #pragma unroll
            for (int nt = 0; nt < 4; nt++)
                #pragma unroll
                for (int r = 0; r < 4; r++)
                    acc1[mt][nt][r] = 0.0f;

        for (int k0 = 0; k0 < DD; k0 += BKS) {
            __syncthreads();
            // stage w1s[32][128]
            {
                const float* w1b = w1 + (size_t)head * DD * II + (size_t)k0 * II + ic;
                #pragma unroll
                for (int i = tid; i < BKS * BI / 4; i += NTHREADS) {
                    int row = i >> 5;
                    int c4  = (i & 31) << 2;
                    float4 v = *(const float4*)(w1b + row * II + c4);
                    *(float4*)(w1s + row * W1_LD + c4) = tf32x4(v);
                }
            }
            __syncthreads();

            #pragma unroll
            for (int kk = 0; kk < BKS; kk += 8) {
                uint32_t a[2][4];
                #pragma unroll
                for (int mt = 0; mt < 2; mt++) {
                    int r  = wm * 32 + mt * 16 + g;
                    int cb = k0 + kk + tg;
                    a[mt][0] = __float_as_uint(sx[r * SX_LD + cb]);
                    a[mt][1] = __float_as_uint(sx[(r + 8) * SX_LD + cb]);
                    a[mt][2] = __float_as_uint(sx[r * SX_LD + cb + 4]);
                    a[mt][3] = __float_as_uint(sx[(r + 8) * SX_LD + cb + 4]);
                }
                uint32_t b[4][2];
                #pragma unroll
                for (int nt = 0; nt < 4; nt++) {
                    int cc = wn * 32 + nt * 8 + g;
                    b[nt][0] = __float_as_uint(w1s[(kk + tg) * W1_LD + cc]);
                    b[nt][1] = __float_as_uint(w1s[(kk + tg + 4) * W1_LD + cc]);
                }
                #pragma unroll
                for (int mt = 0; mt < 2; mt++)
                    #pragma unroll
                    for (int nt = 0; nt < 4; nt++)
                        mma_tf32_16x8x8(acc1[mt][nt], a[mt], b[nt]);
            }
        }

        // ---------- silu + write h chunk to SMEM (tf32-rounded) ----------
        #pragma unroll
        for (int mt = 0; mt < 2; mt++)
            #pragma unroll
            for (int nt = 0; nt < 4; nt++) {
                int r = wm * 32 + mt * 16 + g;
                int c = wn * 32 + nt * 8 + 2 * tg;
                float v0 = silu(acc1[mt][nt][0]);
                float v1 = silu(acc1[mt][nt][1]);
                float v2 = silu(acc1[mt][nt][2]);
                float v3 = silu(acc1[mt][nt][3]);
                hs[r * HS_LD + c]           = __uint_as_float(f32_tf32(v0));
                hs[r * HS_LD + c + 1]       = __uint_as_float(f32_tf32(v1));
                hs[(r + 8) * HS_LD + c]     = __uint_as_float(f32_tf32(v2));
                hs[(r + 8) * HS_LD + c + 1] = __uint_as_float(f32_tf32(v3));
            }

        // ================= GEMM2: o[64][256] += hs[64][128] @ w2[ic:ic+128, :] =================
        for (int k0 = 0; k0 < BI; k0 += BKS) {
            __syncthreads();  // also guards hs writes before first read
            // stage w2s[32][256]
            {
                const float* w2b = w2 + (size_t)head * II * DD + (size_t)(ic + k0) * DD;
                #pragma unroll
                for (int i = tid; i < BKS * DD / 4; i += NTHREADS) {
                    int row = i >> 6;
                    int c4  = (i & 63) << 2;
                    float4 v = *(const float4*)(w2b + row * DD + c4);
                    *(float4*)(w2s + row * W2_LD + c4) = tf32x4(v);
                }
            }
            __syncthreads();

            #pragma unroll
            for (int kk = 0; kk < BKS; kk += 8) {
                uint32_t a[2][4];
                #pragma unroll
                for (int mt = 0; mt < 2; mt++) {
                    int r  = wm * 32 + mt * 16 + g;
                    int cb = k0 + kk + tg;
                    a[mt][0] = __float_as_uint(hs[r * HS_LD + cb]);
                    a[mt][1] = __float_as_uint(hs[(r + 8) * HS_LD + cb]);
                    a[mt][2] = __float_as_uint(hs[r * HS_LD + cb + 4]);
                    a[mt][3] = __float_as_uint(hs[(r + 8) * HS_LD + cb + 4]);
                }
                uint32_t b[8][2];
                #pragma unroll
                for (int nt = 0; nt < 8; nt++) {
                    int cc = wn * 64 + nt * 8 + g;
                    b[nt][0] = __float_as_uint(w2s[(kk + tg) * W2_LD + cc]);
                    b[nt][1] = __float_as_uint(w2s[(kk + tg + 4) * W2_LD + cc]);
                }
                #pragma unroll
                for (int mt = 0; mt < 2; mt++)
                    #pragma unroll
                    for (int nt = 0; nt < 8; nt++)
                        mma_tf32_16x8x8(acc2[mt][nt], a[mt], b[nt]);
            }
        }
    }

    // ---------- epilogue: write o[64][256] ----------
    {
        float* ob = out + ((size_t)head * NN + n0) * DD;
        #pragma unroll
        for (int mt = 0; mt < 2; mt++)
            #pragma unroll
            for (int nt = 0; nt < 8; nt++) {
                int r = wm * 32 + mt * 16 + g;
                int c = wn * 64 + nt * 8 + 2 * tg;
                *(float2*)(ob + (size_t)r * DD + c) =
                    make_float2(acc2[mt][nt][0], acc2[mt][nt][1]);
                *(float2*)(ob + (size_t)(r + 8) * DD + c) =
                    make_float2(acc2[mt][nt][2], acc2[mt][nt][3]);
            }
    }
}

extern "C" void kernel_launch(void* const* d_in, const int* in_sizes, int n_in,
                              void* d_out, int out_size) {
    const float* x  = (const float*)d_in[0];
    const float* w1 = (const float*)d_in[1];
    const float* w2 = (const float*)d_in[2];
    float* out = (float*)d_out;

    cudaFuncSetAttribute(mlp_fused_tf32_kernel,
                         cudaFuncAttributeMaxDynamicSharedMemorySize, SMEM_BYTES);

    dim3 grid(NN / BM, HH);
    mlp_fused_tf32_kernel<<<grid, NTHREADS, SMEM_BYTES>>>(x, w1, w2, out);
}

// round 3
// speedup vs baseline: 1.4385x; 1.4385x over previous
#include <cuda_runtime.h>
#include <cstdint>

#define NTH 256

// shared memory layout (float offsets)
#define XF  0        // x fragments: 4 blk * 32 step * 32 lane * 8 floats = 32768 (128KB)
#define HF  32768    // h fragments: 2 blk * 8 step * 32 lane * 16 floats = 8192 (32KB)
#define W1S 40960    // w1 slabs, 2 buffers * 32*72 = 4608 floats
#define W2S 45568    // w2 slabs, 2 buffers * 16*264 = 8448 floats
#define SMEM_FLOATS (45568 + 8448)
#define SMEM_BYTES  (SMEM_FLOATS * 4)   // 216064 B

__device__ __forceinline__ uint32_t f32_tf32(float x) {
    uint32_t u; asm("cvt.rna.tf32.f32 %0, %1;" : "=r"(u) : "f"(x)); return u;
}
__device__ __forceinline__ float tf32f(float x) { return __uint_as_float(f32_tf32(x)); }
__device__ __forceinline__ float4 cvt4(float4 v) {
    return make_float4(tf32f(v.x), tf32f(v.y), tf32f(v.z), tf32f(v.w));
}
__device__ __forceinline__ void mma_tf32(float c[4], uint32_t a0, uint32_t a1, uint32_t a2, uint32_t a3,
                                         uint32_t b0, uint32_t b1) {
    asm volatile(
        "mma.sync.aligned.m16n8k8.row.col.f32.tf32.tf32.f32 "
        "{%0,%1,%2,%3}, {%4,%5,%6,%7}, {%8,%9}, {%0,%1,%2,%3};\n"
        : "+f"(c[0]), "+f"(c[1]), "+f"(c[2]), "+f"(c[3])
        : "r"(a0), "r"(a1), "r"(a2), "r"(a3), "r"(b0), "r"(b1));
}
__device__ __forceinline__ float silu(float v) { return v / (1.0f + expf(-v)); }

// write one h value into fragment-major layout (with mt-slot rotation for bank-conflict-free reads)
__device__ __forceinline__ void hf_put(float* sm, int r, int cl, float v) {
    int blk   = r >> 6;
    int mtile = (r >> 4) & 3;
    int step  = cl >> 3;
    int cc    = cl & 7;
    int tgp   = cc & 3;
    int hi    = cc >> 2;
    int rh    = (r >> 3) & 1;
    int lanep = ((r & 7) << 2) | tgp;
    int slot  = mtile ^ ((lanep >> 1) & 3);
    sm[HF + (((blk << 3) + step) * 32 + lanep) * 16 + slot * 4 + hi * 2 + rh] = tf32f(v);
}

__global__ __launch_bounds__(NTH, 1)
void mlp_mma_v2(const float* __restrict__ x,
                const float* __restrict__ w1,
                const float* __restrict__ w2,
                float* __restrict__ out) {
    extern __shared__ float sm[];

    const int tid  = threadIdx.x;
    const int wid  = tid >> 5;
    const int lane = tid & 31;
    const int g    = lane >> 2;
    const int tg   = lane & 3;
    const int head = blockIdx.y;
    const int n0   = blockIdx.x * 128;

    const int wm1 = wid >> 1, wn1 = wid & 1;   // GEMM1: 4m x 2n warp grid (32x32 tiles)
    const int wm2 = wid >> 2, wn2 = wid & 3;   // GEMM2: 2m x 4n warp grid (64x64 tiles)

    // ---------------- stage x into fragment-major layout ----------------
    {
        const float* xb = x + ((size_t)head * 8192 + n0) * 256;
        #pragma unroll
        for (int j = 0; j < 32; j++) {
            int f  = tid + j * NTH;      // 0..8191 (float4 index)
            int m  = f >> 6;             // row 0..127
            int c4 = f & 63;             // float4 along K
            float4 v = *(const float4*)(xb + (size_t)m * 256 + c4 * 4);
            int blk = m >> 5, mt = (m >> 4) & 1, gg = m & 7, rh = (m >> 3) & 1;
            int c = c4 * 4;
            int step = c >> 3, hi = (c & 7) >> 2;
            float e0 = tf32f(v.x), e1 = tf32f(v.y), e2 = tf32f(v.z), e3 = tf32f(v.w);
            int slot = mt ^ (gg & 1);
            int base = XF + ((blk * 32 + step) * 32 + gg * 4) * 8 + slot * 4 + hi * 2 + rh;
            sm[base]      = e0;   // tg'=0
            sm[base + 8]  = e1;   // tg'=1 (lane stride = 8 floats)
            sm[base + 16] = e2;
            sm[base + 24] = e3;
        }
    }
    __syncthreads();

    const float* w1h = w1 + (size_t)head * 256 * 1024;
    const float* w2h = w2 + (size_t)head * 1024 * 256;

    float acc2[4][8][4];
    #pragma unroll
    for (int mt = 0; mt < 4; mt++)
        #pragma unroll
        for (int nt = 0; nt < 8; nt++)
            #pragma unroll
            for (int r = 0; r < 4; r++) acc2[mt][nt][r] = 0.0f;

    const int rot1 = g & 1;
    const int rot2 = (lane >> 1) & 3;

    for (int ic = 0; ic < 16; ic++) {
        const int ic0 = ic * 64;

        // ================= GEMM1: z[128x64] = x[128x256] @ w1[:, ic0:ic0+64) =================
        float acc1[2][4][4];
        #pragma unroll
        for (int mt = 0; mt < 2; mt++)
            #pragma unroll
            for (int nt = 0; nt < 4; nt++)
                #pragma unroll
                for (int r = 0; r < 4; r++) acc1[mt][nt][r] = 0.0f;

        // preload slab s=0 (32k x 64n)
        {
            #pragma unroll
            for (int j = 0; j < 2; j++) {
                int f = tid + j * NTH;       // 0..511
                int kr = f >> 4, c4 = f & 15;
                float4 v = *(const float4*)(w1h + (size_t)kr * 1024 + ic0 + c4 * 4);
                *(float4*)(sm + W1S + kr * 72 + c4 * 4) = cvt4(v);
            }
        }
        __syncthreads();

        float4 p[2];
        #pragma unroll
        for (int s = 0; s < 8; s++) {
            const int buf = s & 1;
            if (s < 7) {
                #pragma unroll
                for (int j = 0; j < 2; j++) {
                    int f = tid + j * NTH;
                    int kr = f >> 4, c4 = f & 15;
                    p[j] = *(const float4*)(w1h + (size_t)((s + 1) * 32 + kr) * 1024 + ic0 + c4 * 4);
                }
            }
            const float* wb = sm + W1S + buf * 2304;
            #pragma unroll
            for (int kk = 0; kk < 4; kk++) {
                const int gstep = s * 4 + kk;
                const float* ab = sm + XF + ((wm1 * 32 + gstep) * 32 + lane) * 8;
                float4 A0 = *(const float4*)(ab + ((0 ^ rot1) << 2));
                float4 A1 = *(const float4*)(ab + ((1 ^ rot1) << 2));
                uint32_t a00 = __float_as_uint(A0.x), a01 = __float_as_uint(A0.y),
                         a02 = __float_as_uint(A0.z), a03 = __float_as_uint(A0.w);
                uint32_t a10 = __float_as_uint(A1.x), a11 = __float_as_uint(A1.y),
                         a12 = __float_as_uint(A1.z), a13 = __float_as_uint(A1.w);
                #pragma unroll
                for (int nt = 0; nt < 4; nt++) {
                    int ci = (kk * 8 + tg) * 72 + wn1 * 32 + nt * 8 + g;
                    uint32_t b0 = __float_as_uint(wb[ci]);
                    uint32_t b1 = __float_as_uint(wb[ci + 4 * 72]);
                    mma_tf32(acc1[0][nt], a00, a01, a02, a03, b0, b1);
                    mma_tf32(acc1[1][nt], a10, a11, a12, a13, b0, b1);
                }
            }
            if (s < 7) {
                #pragma unroll
                for (int j = 0; j < 2; j++) {
                    int f = tid + j * NTH;
                    int kr = f >> 4, c4 = f & 15;
                    *(float4*)(sm + W1S + (buf ^ 1) * 2304 + kr * 72 + c4 * 4) = cvt4(p[j]);
                }
            }
            __syncthreads();
        }

        // ---------------- silu -> h fragments ----------------
        #pragma unroll
        for (int mt = 0; mt < 2; mt++)
            #pragma unroll
            for (int nt = 0; nt < 4; nt++) {
                int r0  = wm1 * 32 + mt * 16 + g;
                int cl0 = wn1 * 32 + nt * 8 + 2 * tg;
                hf_put(sm, r0,     cl0,     silu(acc1[mt][nt][0]));
                hf_put(sm, r0,     cl0 + 1, silu(acc1[mt][nt][1]));
                hf_put(sm, r0 + 8, cl0,     silu(acc1[mt][nt][2]));
                hf_put(sm, r0 + 8, cl0 + 1, silu(acc1[mt][nt][3]));
            }
        __syncthreads();

        // ================= GEMM2: o[128x256] += h[128x64] @ w2[ic0:ic0+64, :) =================
        // preload slab t=0 (16k x 256n)
        {
            #pragma unroll
            for (int j = 0; j < 4; j++) {
                int f = tid + j * NTH;       // 0..1023
                int kr = f >> 6, c4 = f & 63;
                float4 v = *(const float4*)(w2h + (size_t)(ic0 + kr) * 256 + c4 * 4);
                *(float4*)(sm + W2S + kr * 264 + c4 * 4) = cvt4(v);
            }
        }
        __syncthreads();

        float4 q[4];
        #pragma unroll
        for (int t = 0; t < 4; t++) {
            const int buf = t & 1;
            if (t < 3) {
                #pragma unroll
                for (int j = 0; j < 4; j++) {
                    int f = tid + j * NTH;
                    int kr = f >> 6, c4 = f & 63;
                    q[j] = *(const float4*)(w2h + (size_t)(ic0 + (t + 1) * 16 + kr) * 256 + c4 * 4);
                }
            }
            const float* wb = sm + W2S + buf * 4224;
            #pragma unroll
            for (int kk = 0; kk < 2; kk++) {
                const int gstep = t * 2 + kk;
                const float* ab = sm + HF + ((wm2 * 8 + gstep) * 32 + lane) * 16;
                float4 A[4];
                #pragma unroll
                for (int mt = 0; mt < 4; mt++)
                    A[mt] = *(const float4*)(ab + ((mt ^ rot2) << 2));
                #pragma unroll
                for (int nt = 0; nt < 8; nt++) {
                    int ci = (kk * 8 + tg) * 264 + wn2 * 64 + nt * 8 + g;
                    uint32_t b0 = __float_as_uint(wb[ci]);
                    uint32_t b1 = __float_as_uint(wb[ci + 4 * 264]);
                    #pragma unroll
                    for (int mt = 0; mt < 4; mt++)
                        mma_tf32(acc2[mt][nt],
                                 __float_as_uint(A[mt].x), __float_as_uint(A[mt].y),
                                 __float_as_uint(A[mt].z), __float_as_uint(A[mt].w),
                                 b0, b1);
                }
            }
            if (t < 3) {
                #pragma unroll
                for (int j = 0; j < 4; j++) {
                    int f = tid + j * NTH;
                    int kr = f >> 6, c4 = f & 63;
                    *(float4*)(sm + W2S + (buf ^ 1) * 4224 + kr * 264 + c4 * 4) = cvt4(q[j]);
                }
            }
            __syncthreads();
        }
    }

    // ---------------- epilogue ----------------
    {
        float* ob = out + ((size_t)head * 8192 + n0) * 256;
        #pragma unroll
        for (int mt = 0; mt < 4; mt++)
            #pragma unroll
            for (int nt = 0; nt < 8; nt++) {
                int r = wm2 * 64 + mt * 16 + g;
                int c = wn2 * 64 + nt * 8 + 2 * tg;
                *(float2*)(ob + (size_t)r * 256 + c) =
                    make_float2(acc2[mt][nt][0], acc2[mt][nt][1]);
                *(float2*)(ob + (size_t)(r + 8) * 256 + c) =
                    make_float2(acc2[mt][nt][2], acc2[mt][nt][3]);
            }
    }
}

extern "C" void kernel_launch(void* const* d_in, const int* in_sizes, int n_in,
                              void* d_out, int out_size) {
    const float* x  = (const float*)d_in[0];
    const float* w1 = (const float*)d_in[1];
    const float* w2 = (const float*)d_in[2];
    float* out = (float*)d_out;

    cudaFuncSetAttribute(mlp_mma_v2,
                         cudaFuncAttributeMaxDynamicSharedMemorySize, SMEM_BYTES);

    dim3 grid(8192 / 128, 16);
    mlp_mma_v2<<<grid, NTH, SMEM_BYTES>>>(x, w1, w2, out);
}